// round 12
// baseline (speedup 1.0000x reference)
#include <cuda_runtime.h>
#include <cstdint>

// Problem constants (fixed by setup_inputs): B=1, H=32, Lq=512, Lk=4096, group_size=4
#define H       32
#define LQ      512
#define LK      4096
#define WORDS   128            // LK / 32
#define KSEL    819            // int(0.2 * 4096)
#define THRESH  1638           // min(2*819, int(0.75*4096))
#define GS      4
#define NG      8              // H / GS
#define NOT_CHOSEN (1 << 30)
#define MAXCAND 64
#define NT      512            // threads per k_topk block (8 elems/thread)

// Key-domain window for the 819th-largest of 4096 i.i.d. N(0,1) samples.
// Pivot value concentrates at 0.8416 +- 0.022; window [0.70, 1.00] is ~7 sigma.
// fkey is linear in value on [0.5, 1.0) (one exponent region), so key-binning
// is exact value-binning. Exact fallback handles anything outside the window.
#define KHI 0xBF800000u        // fkey(1.0f)
#define KLO 0xBF333333u        // fkey(0.7f)
#define BSHIFT 14              // bin width = 2^14 keys = 2^-10 in value
#define HSIZE 320              // padded: 10 bins/lane * 32 lanes
#define BPL 10

// Scratch (device globals; no allocation allowed)
__device__ unsigned g_masks[(size_t)H * LQ * WORDS];   // 8 MB of top-k bitsets
__device__ unsigned g_hunion[H * WORDS];
__device__ int      g_nsel[H];
__device__ int      g_gcnt[NG];
__device__ int      g_done[H];       // barrier-1 flags (reset by k_topk block 0)
__device__ int      g_done2[H];      // barrier-2 flags
__device__ int      g_done3[NG];     // density flags

// Order-preserving float -> uint32 map (larger float => larger key)
__device__ __forceinline__ unsigned fkey(float f) {
    unsigned u = __float_as_uint(f);
    return (u & 0x80000000u) ? ~u : (u | 0x80000000u);
}

// ---------------------------------------------------------------------------
// Kernel 1: per-row exact top-k mask (round-7 algorithm, re-geometried).
// 512 threads x 8 elements: halves per-thread registers + serial chains so
// 4 blocks/SM (100% occupancy) fit; the R10 profile showed this kernel is
// stall-limited (issue 59%, no pipe saturated) at 62.5% occupancy.
// Windowed 308-bin key-domain histogram + tiny exact refinement, exact
// binary-search fallback. Also zeros this row of the output.
// grid = H*LQ blocks; each block owns one row of 4096 floats.
// ---------------------------------------------------------------------------
__global__ void __launch_bounds__(NT, 4) k_topk(const float* __restrict__ scores,
                                                float* __restrict__ out) {
    __shared__ unsigned hist[HSIZE];
    __shared__ unsigned cand[MAXCAND];
    __shared__ unsigned s_cnthi, s_ncand, s_pivotkey, s_tot;
    __shared__ int s_bin, s_rem;

    const int row  = blockIdx.x;
    const int t    = threadIdx.x;
    const int lane = t & 31, warp = t >> 5;

    // Reset k_tail flags once per launch (kernel boundary orders this vs k_tail)
    if (row == 0) {
        if (t < H)  { g_done[t] = 0; g_done2[t] = 0; }
        if (t < NG) g_done3[t] = 0;
    }

    if (t < HSIZE) hist[t] = 0u;
    if (t == 0) { s_cnthi = 0u; s_ncand = 0u; s_bin = -2; }
    __syncthreads();

    // Load 8 elements/thread as keys (coalesced float4); zero the output row.
    unsigned key[8];
    const float4* src  = (const float4*)(scores + (size_t)row * LK);
    float4*       zdst = (float4*)(out + (size_t)row * LK);
    #pragma unroll
    for (int i = 0; i < 2; i++) {
        float4 v = __ldcs(src + t + i * NT);
        key[4 * i + 0] = fkey(v.x); key[4 * i + 1] = fkey(v.y);
        key[4 * i + 2] = fkey(v.z); key[4 * i + 3] = fkey(v.w);
    }
    const float4 z = make_float4(0.f, 0.f, 0.f, 0.f);
    #pragma unroll
    for (int i = 0; i < 2; i++) __stcs(zdst + t + i * NT, z);

    // Count above-window; histogram in-window keys (~8% of row)
    int chi = 0;
    #pragma unroll
    for (int e = 0; e < 8; e++) {
        unsigned k = key[e];
        if (k > KHI) chi++;
        else if (k >= KLO) atomicAdd(&hist[(KHI - k) >> BSHIFT], 1u);
    }
    #pragma unroll
    for (int off = 16; off; off >>= 1)
        chi += __shfl_down_sync(0xffffffffu, chi, off);
    if (lane == 0) atomicAdd(&s_cnthi, (unsigned)chi);
    __syncthreads();

    // One-warp cumulative-from-top scan over the bins (bin 0 = largest values)
    if (warp == 0) {
        const unsigned cnthi = s_cnthi;
        unsigned part = 0;
        #pragma unroll
        for (int i = 0; i < BPL; i++) part += hist[lane * BPL + i];
        unsigned pfx = part;
        #pragma unroll
        for (int s = 1; s < 32; s <<= 1) {
            unsigned v = __shfl_up_sync(0xffffffffu, pfx, s);
            if (lane >= s) pfx += v;
        }
        unsigned excl  = pfx - part;
        unsigned total = __shfl_sync(0xffffffffu, pfx, 31);
        unsigned base  = cnthi + excl;
        if (base < KSEL && base + part >= KSEL) {
            unsigned acc = base;
            #pragma unroll
            for (int i = 0; i < BPL; i++) {
                unsigned hv = hist[lane * BPL + i];
                if (acc + hv >= KSEL) { s_bin = lane * BPL + i; s_rem = (int)(KSEL - acc); break; }
                acc += hv;
            }
        }
        if (lane == 0 && (cnthi >= KSEL || cnthi + total < KSEL)) s_bin = -1; // fallback
    }
    __syncthreads();

    const int bin = s_bin;

    if (bin >= 0) {
        // Gather pivot-bin candidates (expected ~1, bin width 2^-10 in value)
        #pragma unroll
        for (int e = 0; e < 8; e++) {
            unsigned k = key[e];
            if (k <= KHI && k >= KLO && (int)((KHI - k) >> BSHIFT) == bin) {
                unsigned p = atomicAdd(&s_ncand, 1u);
                if (p < MAXCAND) cand[p] = k;
            }
        }
        __syncthreads();
        unsigned nc = s_ncand;
        if (nc <= MAXCAND) {
            const int rem = s_rem;
            if (t < (int)nc) {
                unsigned me = cand[t];
                int gcnt = 0, eq = 0;
                for (unsigned j = 0; j < nc; j++) {
                    unsigned v = cand[j];
                    gcnt += (v > me);
                    eq   += (v == me);
                }
                if (gcnt < rem && gcnt + eq >= rem) s_pivotkey = me;
            }
        } else {
            if (t == 0) s_bin = -1;   // overflow -> fallback
        }
        __syncthreads();
    }

    if (s_bin < 0) {
        // Exact fallback: MSB-first binary search on keys
        unsigned piv = 0;
        for (int bit = 31; bit >= 0; --bit) {
            unsigned candv = piv | (1u << bit);
            int c = 0;
            #pragma unroll
            for (int e = 0; e < 8; e++) c += (key[e] >= candv);
            #pragma unroll
            for (int off = 16; off; off >>= 1)
                c += __shfl_down_sync(0xffffffffu, c, off);
            if (t == 0) s_tot = 0u;
            __syncthreads();
            if (lane == 0) atomicAdd(&s_tot, (unsigned)c);
            __syncthreads();
            if (s_tot >= KSEL) piv = candv;
            __syncthreads();
        }
        if (t == 0) s_pivotkey = piv;
        __syncthreads();
    }

    const unsigned pivot = s_pivotkey;

    // Membership: float4 index f = t + 512i covers elements [4f, 4f+4).
    // OR-merge 4-bit nibbles across each 8-lane octet with 3 xor-shuffles;
    // octet leader writes mask word f>>3. No smem, no barrier.
    unsigned* mrow = g_masks + (size_t)row * WORDS;
    #pragma unroll
    for (int i = 0; i < 2; i++) {
        const int f = t + i * NT;
        unsigned nib = 0;
        #pragma unroll
        for (int m = 0; m < 4; m++) nib |= (unsigned)(key[4 * i + m] >= pivot) << m;
        unsigned wv = nib << (4 * (lane & 7));
        wv |= __shfl_xor_sync(0xffffffffu, wv, 1);
        wv |= __shfl_xor_sync(0xffffffffu, wv, 2);
        wv |= __shfl_xor_sync(0xffffffffu, wv, 4);
        if ((lane & 7) == 0) mrow[f >> 3] = wv;
    }
}

// ---------------------------------------------------------------------------
// Kernel 2 (fused tail): one block per head (32 blocks, always co-resident).
// Phase 1: per-head back-to-front scan (parallel across heads). Spin barrier.
// n_stop. Phase 2: per-head union. Spin barrier. Group-OR + last-row write
// (spread over 32 blocks) + density. All __syncthreads() unconditional.
// (Round-7 structure verbatim — measured 11.5 us.)
// ---------------------------------------------------------------------------
__global__ void __launch_bounds__(256) k_tail(float* __restrict__ out, int write_density) {
    const int h = blockIdx.x;          // 0..31
    const int g = h / GS;
    const int t = threadIdx.x;
    const int lane = t & 31, warp = t >> 5;
    __shared__ int s_found, s_cnt, s_nstop;
    __shared__ int ws[8];
    __shared__ unsigned su[WORDS];

    // ---- Phase 1: nsel for head h ----
    if (t == 0) { s_found = 0; s_cnt = 0; }
    __syncthreads();
    const unsigned* base = g_masks + (size_t)h * LQ * WORDS;
    unsigned un = 0;
    for (int n = 1; n <= LQ; n++) {
        unsigned m = (t < 128) ? base[(size_t)(LQ - n) * WORDS + t] : 0u;
        int add = __popc(m & ~un);
        un |= m;
        #pragma unroll
        for (int off = 16; off; off >>= 1)
            add += __shfl_down_sync(0xffffffffu, add, off);
        if (lane == 0) ws[warp] = add;
        __syncthreads();
        if (t == 0) {
            int sum = 0;
            #pragma unroll
            for (int w = 0; w < 8; w++) sum += ws[w];
            s_cnt += sum;
            if (!s_found && s_cnt >= THRESH) s_found = n;
        }
        __syncthreads();
        if (s_found) break;            // uniform: decided from shared state
    }
    if (t == 0) {
        g_nsel[h] = s_found ? s_found : NOT_CHOSEN;
        __threadfence();
        atomicExch(&g_done[h], 1);
    }

    // ---- Global barrier 1 (32 co-resident blocks) ----
    if (t < H) {
        volatile int* vd = g_done;
        while (vd[t] == 0) {}
    }
    __syncthreads();
    __threadfence();

    // n_stop from all heads (warp 0)
    if (warp == 0) {
        int v  = g_nsel[lane];
        int ch = (v < NOT_CHOSEN) ? 1 : 0;
        int mx = ch ? v : 1;
        #pragma unroll
        for (int off = 16; off; off >>= 1) {
            ch = min(ch, __shfl_down_sync(0xffffffffu, ch, off));
            mx = max(mx, __shfl_down_sync(0xffffffffu, mx, off));
        }
        if (lane == 0) s_nstop = ch ? mx : LQ;
    }
    __syncthreads();

    // ---- Phase 2: union of last n_stop rows of head h ----
    const int ns = s_nstop;
    if (t < 128) {
        unsigned u = 0;
        for (int n = 1; n <= ns; n++)
            u |= base[(size_t)(LQ - n) * WORDS + t];
        g_hunion[h * WORDS + t] = u;
    }
    __threadfence();
    __syncthreads();
    if (t == 0) atomicExch(&g_done2[h], 1);

    // ---- Global barrier 2 ----
    if (t < H) {
        volatile int* vd = g_done2;
        while (vd[t] == 0) {}
    }
    __syncthreads();
    __threadfence();

    // Group-OR for this head's group
    if (t < 128) {
        unsigned gu = g_hunion[(g * GS + 0) * WORDS + t]
                    | g_hunion[(g * GS + 1) * WORDS + t]
                    | g_hunion[(g * GS + 2) * WORDS + t]
                    | g_hunion[(g * GS + 3) * WORDS + t];
        su[t] = gu;
        int c = __popc(gu);
        #pragma unroll
        for (int off = 16; off; off >>= 1)
            c += __shfl_down_sync(0xffffffffu, c, off);
        if (lane == 0) ws[warp] = c;
    }
    __syncthreads();

    // Last-row values for head h (float4 stores, 16 KB per block)
    const float MINV = -3.402823466e38f;  // finfo(float32).min
    float* orow = out + ((size_t)h * LQ + (LQ - 1)) * LK;
    #pragma unroll
    for (int i = 0; i < 4; i++) {
        int c4 = t + i * 256;              // float4 index; cols 4*c4..4*c4+3
        unsigned w = su[c4 >> 3];
        float4 v;
        v.x = ((w >> ((4 * c4 + 0) & 31)) & 1u) ? 0.0f : MINV;
        v.y = ((w >> ((4 * c4 + 1) & 31)) & 1u) ? 0.0f : MINV;
        v.z = ((w >> ((4 * c4 + 2) & 31)) & 1u) ? 0.0f : MINV;
        v.w = ((w >> ((4 * c4 + 3) & 31)) & 1u) ? 0.0f : MINV;
        ((float4*)orow)[c4] = v;
    }

    // Density: group-leader blocks publish; block 0 aggregates
    if (write_density) {
        if ((h & (GS - 1)) == 0 && t == 0) {
            g_gcnt[g] = GS * (ws[0] + ws[1] + ws[2] + ws[3]);
            __threadfence();
            atomicExch(&g_done3[g], 1);
        }
        if (h == 0) {
            if (t < NG) {
                volatile int* vd = g_done3;
                while (vd[t] == 0) {}
            }
            __syncthreads();
            __threadfence();
            if (t == 0) {
                int total = 0;
                #pragma unroll
                for (int i = 0; i < NG; i++) total += g_gcnt[i];
                out[(size_t)H * LQ * LK] = (float)total / (float)(H * LK);
            }
        }
    }
}

// ---------------------------------------------------------------------------
extern "C" void kernel_launch(void* const* d_in, const int* in_sizes, int n_in,
                              void* d_out, int out_size) {
    const float* scores = (const float*)d_in[0];
    float* out = (float*)d_out;

    k_topk<<<H * LQ, NT>>>(scores, out);   // also zeros output rows + resets flags
    k_tail<<<H, 256>>>(out, out_size > H * LQ * LK ? 1 : 0);
}

// round 13
// speedup vs baseline: 1.1290x; 1.1290x over previous
#include <cuda_runtime.h>
#include <cstdint>

// Problem constants (fixed by setup_inputs): B=1, H=32, Lq=512, Lk=4096, group_size=4
#define H       32
#define LQ      512
#define LK      4096
#define WORDS   128            // LK / 32
#define KSEL    819            // int(0.2 * 4096)
#define THRESH  1638           // min(2*819, int(0.75*4096))
#define GS      4
#define NG      8              // H / GS
#define NOT_CHOSEN (1 << 30)
#define MAXCAND 64

// Raw-bits window for the 819th-largest of 4096 i.i.d. N(0,1) samples.
// Pivot value concentrates at 0.8416 +- 0.022; window [0.70, 1.00] is ~7 sigma.
// All in-window values are positive floats, so SIGNED integer compares on the
// raw bits are exact float compares (negatives have the sign bit => INT-negative
// => below any positive pivot). Bin width 2^14 ulps = 2^-10 in value; 308 bins.
// The exact key-domain fallback handles anything outside the window.
#define IWHI 0x3F800000        // bits(1.0f)
#define IWLO 0x3F333333        // bits(0.7f)
#define BSHIFT 14
#define HSIZE 320              // padded: 10 bins/lane * 32 lanes (308 used)
#define BPL 10

// Scratch (device globals; no allocation allowed)
__device__ unsigned g_masks[(size_t)H * LQ * WORDS];   // 8 MB of top-k bitsets
__device__ unsigned g_hunion[H * WORDS];
__device__ int      g_nsel[H];
__device__ int      g_gcnt[NG];
__device__ int      g_done[H];       // barrier-1 flags (reset by k_topk block 0)
__device__ int      g_done2[H];      // barrier-2 flags
__device__ int      g_done3[NG];     // density flags

// Order-preserving float-bits -> uint32 key map (fallback path only)
__device__ __forceinline__ unsigned fkey_bits(unsigned u) {
    return (u & 0x80000000u) ? ~u : (u | 0x80000000u);
}
__device__ __forceinline__ int unfkey_bits(unsigned k) {
    return (int)((k & 0x80000000u) ? (k & 0x7FFFFFFFu) : ~k);
}

// ---------------------------------------------------------------------------
// Kernel 1: per-row exact top-k mask (round-7 structure; raw-int domain —
// no per-element key conversion). Windowed 308-bin histogram + tiny exact
// refinement, exact binary-search fallback. Zeros this row of the output.
// grid = H*LQ blocks, 256 threads; each block owns one row of 4096 floats.
// ---------------------------------------------------------------------------
__global__ void __launch_bounds__(256) k_topk(const float* __restrict__ scores,
                                              float* __restrict__ out) {
    __shared__ unsigned hist[HSIZE];
    __shared__ int      cand[MAXCAND];   // raw bits of pivot-bin candidates
    __shared__ unsigned s_cnthi, s_ncand, s_tot;
    __shared__ int s_bin, s_rem, s_pivot;

    const int row  = blockIdx.x;
    const int t    = threadIdx.x;
    const int lane = t & 31, warp = t >> 5;

    // Reset k_tail flags once per launch (kernel boundary orders this vs k_tail)
    if (row == 0) {
        if (t < H)  { g_done[t] = 0; g_done2[t] = 0; }
        if (t < NG) g_done3[t] = 0;
    }

    hist[t] = 0u;
    if (t < HSIZE - 256) hist[256 + t] = 0u;
    if (t == 0) { s_cnthi = 0u; s_ncand = 0u; s_bin = -2; }
    __syncthreads();

    // Load 16 elements/thread as raw bits (coalesced 16B); zero the output row.
    int ix[16];
    const int4* src  = (const int4*)(scores + (size_t)row * LK);
    float4*     zdst = (float4*)(out + (size_t)row * LK);
    #pragma unroll
    for (int i = 0; i < 4; i++) {
        int4 v = __ldcs(src + t + i * 256);
        ix[4 * i + 0] = v.x; ix[4 * i + 1] = v.y;
        ix[4 * i + 2] = v.z; ix[4 * i + 3] = v.w;
    }
    const float4 z = make_float4(0.f, 0.f, 0.f, 0.f);
    #pragma unroll
    for (int i = 0; i < 4; i++) __stcs(zdst + t + i * 256, z);

    // Count above-window; histogram in-window bits (~8% of row). Signed
    // compares: negatives are INT-negative and fall below the window free.
    int chi = 0;
    #pragma unroll
    for (int e = 0; e < 16; e++) {
        int k = ix[e];
        if (k > IWHI) chi++;
        else if (k >= IWLO) atomicAdd(&hist[(unsigned)(IWHI - k) >> BSHIFT], 1u);
    }
    #pragma unroll
    for (int off = 16; off; off >>= 1)
        chi += __shfl_down_sync(0xffffffffu, chi, off);
    if (lane == 0) atomicAdd(&s_cnthi, (unsigned)chi);
    __syncthreads();

    // One-warp cumulative-from-top scan over the bins (bin 0 = largest values)
    if (warp == 0) {
        const unsigned cnthi = s_cnthi;
        unsigned part = 0;
        #pragma unroll
        for (int i = 0; i < BPL; i++) part += hist[lane * BPL + i];
        unsigned pfx = part;
        #pragma unroll
        for (int s = 1; s < 32; s <<= 1) {
            unsigned v = __shfl_up_sync(0xffffffffu, pfx, s);
            if (lane >= s) pfx += v;
        }
        unsigned excl  = pfx - part;
        unsigned total = __shfl_sync(0xffffffffu, pfx, 31);
        unsigned base  = cnthi + excl;
        if (base < KSEL && base + part >= KSEL) {
            unsigned acc = base;
            #pragma unroll
            for (int i = 0; i < BPL; i++) {
                unsigned hv = hist[lane * BPL + i];
                if (acc + hv >= KSEL) { s_bin = lane * BPL + i; s_rem = (int)(KSEL - acc); break; }
                acc += hv;
            }
        }
        if (lane == 0 && (cnthi >= KSEL || cnthi + total < KSEL)) s_bin = -1; // fallback
    }
    __syncthreads();

    const int bin = s_bin;

    if (bin >= 0) {
        // Gather pivot-bin candidates (expected ~1), exact rank-select
        #pragma unroll
        for (int e = 0; e < 16; e++) {
            int k = ix[e];
            if (k <= IWHI && k >= IWLO && (int)((unsigned)(IWHI - k) >> BSHIFT) == bin) {
                unsigned p = atomicAdd(&s_ncand, 1u);
                if (p < MAXCAND) cand[p] = k;
            }
        }
        __syncthreads();
        unsigned nc = s_ncand;
        if (nc <= MAXCAND) {
            const int rem = s_rem;
            if (t < (int)nc) {
                int me = cand[t];       // positive bits: signed compare = float compare
                int gcnt = 0, eq = 0;
                for (unsigned j = 0; j < nc; j++) {
                    int v = cand[j];
                    gcnt += (v > me);
                    eq   += (v == me);
                }
                if (gcnt < rem && gcnt + eq >= rem) s_pivot = me;
            }
        } else {
            if (t == 0) s_bin = -1;   // overflow -> fallback
        }
        __syncthreads();
    }

    if (s_bin < 0) {
        // Exact fallback: MSB-first binary search on order-preserving keys
        unsigned piv = 0;
        for (int bit = 31; bit >= 0; --bit) {
            unsigned candv = piv | (1u << bit);
            int c = 0;
            #pragma unroll
            for (int e = 0; e < 16; e++) c += (fkey_bits((unsigned)ix[e]) >= candv);
            #pragma unroll
            for (int off = 16; off; off >>= 1)
                c += __shfl_down_sync(0xffffffffu, c, off);
            if (t == 0) s_tot = 0u;
            __syncthreads();
            if (lane == 0) atomicAdd(&s_tot, (unsigned)c);
            __syncthreads();
            if (s_tot >= KSEL) piv = candv;
            __syncthreads();
        }
        if (t == 0) s_pivot = unfkey_bits(piv);
        __syncthreads();
    }

    const int pivot = s_pivot;

    // Membership: element 4t+1024i+m; signed-int compare vs pivot bits.
    // OR-merge 4-bit nibbles across each 8-lane octet with 3 xor-shuffles;
    // octet leader writes the 32-bit word. No smem, no barrier.
    unsigned* mrow = g_masks + (size_t)row * WORDS;
    #pragma unroll
    for (int i = 0; i < 4; i++) {
        unsigned nib = 0;
        #pragma unroll
        for (int m = 0; m < 4; m++) nib |= (unsigned)(ix[4 * i + m] >= pivot) << m;
        unsigned wv = nib << (4 * (lane & 7));
        wv |= __shfl_xor_sync(0xffffffffu, wv, 1);
        wv |= __shfl_xor_sync(0xffffffffu, wv, 2);
        wv |= __shfl_xor_sync(0xffffffffu, wv, 4);
        if ((lane & 7) == 0) mrow[32 * i + 4 * warp + (lane >> 3)] = wv;
    }
}

// ---------------------------------------------------------------------------
// Kernel 2 (fused tail): one block per head (32 co-resident blocks).
// Phase 1 is WARP-0-ONLY (lane owns 4 mask words; per-row union+popc is pure
// shfl — no block barriers in the loop). Phase 2 continues from the phase-1
// union registers. Two global flag barriers for the n_stop coupling.
// ---------------------------------------------------------------------------
__global__ void __launch_bounds__(256) k_tail(float* __restrict__ out, int write_density) {
    const int h = blockIdx.x;          // 0..31
    const int g = h / GS;
    const int t = threadIdx.x;
    const int lane = t & 31, warp = t >> 5;
    __shared__ int ws[8];
    __shared__ unsigned su[WORDS];

    const unsigned* base = g_masks + (size_t)h * LQ * WORDS;

    // ---- Phase 1 (warp 0 only): nsel for head h; all-shfl loop ----
    int found = 0;
    unsigned un0 = 0, un1 = 0, un2 = 0, un3 = 0;
    if (warp == 0) {
        int cnt = 0;
        for (int n = 1; n <= LQ && !found; n++) {
            const unsigned* r = base + (size_t)(LQ - n) * WORDS;
            unsigned m0 = r[lane], m1 = r[lane + 32], m2 = r[lane + 64], m3 = r[lane + 96];
            int add = __popc(m0 & ~un0) + __popc(m1 & ~un1)
                    + __popc(m2 & ~un2) + __popc(m3 & ~un3);
            un0 |= m0; un1 |= m1; un2 |= m2; un3 |= m3;
            #pragma unroll
            for (int off = 16; off; off >>= 1)
                add += __shfl_down_sync(0xffffffffu, add, off);
            add = __shfl_sync(0xffffffffu, add, 0);     // broadcast row total
            cnt += add;
            if (cnt >= THRESH) found = n;               // uniform across warp
        }
        if (lane == 0) {
            g_nsel[h] = found ? found : NOT_CHOSEN;
            __threadfence();
            atomicExch(&g_done[h], 1);
        }
    }

    // ---- Global barrier 1 (32 co-resident blocks; warp 0 polls) ----
    if (t < H) {
        volatile int* vd = g_done;
        while (vd[t] == 0) {}
    }
    __syncthreads();
    __threadfence();

    // ---- n_stop + Phase 2 (warp 0): continue union from found+1 to n_stop ----
    if (warp == 0) {
        int v  = g_nsel[lane];
        int ch = (v < NOT_CHOSEN) ? 1 : 0;
        int mx = ch ? v : 1;
        #pragma unroll
        for (int off = 16; off; off >>= 1) {
            ch = min(ch, __shfl_down_sync(0xffffffffu, ch, off));
            mx = max(mx, __shfl_down_sync(0xffffffffu, mx, off));
        }
        int ns = __shfl_sync(0xffffffffu, ch ? mx : LQ, 0);
        // un covers 'found' rows if chosen, else all LQ rows (start > ns then)
        for (int n = (found ? found : LQ) + 1; n <= ns; n++) {
            const unsigned* r = base + (size_t)(LQ - n) * WORDS;
            un0 |= r[lane]; un1 |= r[lane + 32]; un2 |= r[lane + 64]; un3 |= r[lane + 96];
        }
        g_hunion[h * WORDS + lane]      = un0;
        g_hunion[h * WORDS + lane + 32] = un1;
        g_hunion[h * WORDS + lane + 64] = un2;
        g_hunion[h * WORDS + lane + 96] = un3;
        __threadfence();
        if (lane == 0) atomicExch(&g_done2[h], 1);
    }

    // ---- Global barrier 2 ----
    if (t < H) {
        volatile int* vd = g_done2;
        while (vd[t] == 0) {}
    }
    __syncthreads();
    __threadfence();

    // Group-OR for this head's group
    if (t < 128) {
        unsigned gu = g_hunion[(g * GS + 0) * WORDS + t]
                    | g_hunion[(g * GS + 1) * WORDS + t]
                    | g_hunion[(g * GS + 2) * WORDS + t]
                    | g_hunion[(g * GS + 3) * WORDS + t];
        su[t] = gu;
        int c = __popc(gu);
        #pragma unroll
        for (int off = 16; off; off >>= 1)
            c += __shfl_down_sync(0xffffffffu, c, off);
        if (lane == 0) ws[warp] = c;
    }
    __syncthreads();

    // Last-row values for head h (float4 stores, 16 KB per block)
    const float MINV = -3.402823466e38f;  // finfo(float32).min
    float* orow = out + ((size_t)h * LQ + (LQ - 1)) * LK;
    #pragma unroll
    for (int i = 0; i < 4; i++) {
        int c4 = t + i * 256;              // float4 index; cols 4*c4..4*c4+3
        unsigned w = su[c4 >> 3];
        float4 v;
        v.x = ((w >> ((4 * c4 + 0) & 31)) & 1u) ? 0.0f : MINV;
        v.y = ((w >> ((4 * c4 + 1) & 31)) & 1u) ? 0.0f : MINV;
        v.z = ((w >> ((4 * c4 + 2) & 31)) & 1u) ? 0.0f : MINV;
        v.w = ((w >> ((4 * c4 + 3) & 31)) & 1u) ? 0.0f : MINV;
        ((float4*)orow)[c4] = v;
    }

    // Density: group-leader blocks publish; block 0 aggregates
    if (write_density) {
        if ((h & (GS - 1)) == 0 && t == 0) {
            g_gcnt[g] = GS * (ws[0] + ws[1] + ws[2] + ws[3]);
            __threadfence();
            atomicExch(&g_done3[g], 1);
        }
        if (h == 0) {
            if (t < NG) {
                volatile int* vd = g_done3;
                while (vd[t] == 0) {}
            }
            __syncthreads();
            __threadfence();
            if (t == 0) {
                int total = 0;
                #pragma unroll
                for (int i = 0; i < NG; i++) total += g_gcnt[i];
                out[(size_t)H * LQ * LK] = (float)total / (float)(H * LK);
            }
        }
    }
}

// ---------------------------------------------------------------------------
extern "C" void kernel_launch(void* const* d_in, const int* in_sizes, int n_in,
                              void* d_out, int out_size) {
    const float* scores = (const float*)d_in[0];
    float* out = (float*)d_out;

    k_topk<<<H * LQ, 256>>>(scores, out);   // also zeros output rows + resets flags
    k_tail<<<H, 256>>>(out, out_size > H * LQ * LK ? 1 : 0);
}

// round 14
// speedup vs baseline: 2.3957x; 2.1219x over previous
#include <cuda_runtime.h>
#include <cstdint>

// Problem constants (fixed by setup_inputs): B=1, H=32, Lq=512, Lk=4096, group_size=4
#define H       32
#define LQ      512
#define LK      4096
#define WORDS   128            // LK / 32
#define KSEL    819            // int(0.2 * 4096)
#define THRESH  1638           // min(2*819, int(0.75*4096))
#define GS      4
#define NG      8              // H / GS
#define NOT_CHOSEN (1 << 30)
#define MAXCAND 64

// Raw-bits window for the 819th-largest of 4096 i.i.d. N(0,1) samples.
// Pivot concentrates at 0.8416 +- 0.022; [0.70, 1.00] is ~7 sigma. In-window
// values are positive floats => SIGNED int compares on raw bits are exact
// float compares (negatives are INT-negative => below any positive pivot).
// Bin width 2^14 ulps = 2^-10 in value; 308 bins. Exact fallback otherwise.
#define IWHI 0x3F800000        // bits(1.0f)
#define IWLO 0x3F333333        // bits(0.7f)
#define BSHIFT 14
#define HSIZE 320              // padded: 10 bins/lane * 32 lanes (308 used)
#define BPL 10

// Scratch (device globals; zero-init at load; no allocation allowed).
// g_bar1 is MONOTONIC: every execution adds exactly H, so "multiple of H"
// marks barrier completion; no reset needed across graph replays.
__device__ unsigned g_hunion[H * WORDS];
__device__ int      g_nsel[H];
__device__ unsigned g_bar1;

// Order-preserving float-bits <-> key map (exact-fallback path only)
__device__ __forceinline__ unsigned fkey_bits(unsigned u) {
    return (u & 0x80000000u) ? ~u : (u | 0x80000000u);
}
__device__ __forceinline__ int unfkey_bits(unsigned k) {
    return (int)((k & 0x80000000u) ? (k & 0x7FFFFFFFu) : ~k);
}

// Shared-memory state for one block of k_sel
struct ShState {
    unsigned hist[HSIZE];
    int      cand[MAXCAND];
    unsigned su[WORDS];        // running union bitset for this head
    unsigned s_cnthi, s_ncand, s_tot;
    int s_bin, s_rem, s_pivot, s_cnt, s_found, s_nstop;
};

// ---------------------------------------------------------------------------
// One row's exact top-k membership, ORed into S.su with incremental popcount
// into S.s_cnt. Champion (R12) row body: windowed 308-bin raw-int histogram,
// tiny exact refinement, exact binary-search fallback. 256 threads.
// ---------------------------------------------------------------------------
__device__ __forceinline__ void row_union(ShState& S, const int4* __restrict__ src,
                                          int t, int lane, int warp) {
    S.hist[t] = 0u;
    if (t < HSIZE - 256) S.hist[256 + t] = 0u;
    if (t == 0) { S.s_cnthi = 0u; S.s_ncand = 0u; S.s_bin = -2; }
    __syncthreads();

    // Load 16 elements/thread as raw bits (coalesced 16B)
    int ix[16];
    #pragma unroll
    for (int i = 0; i < 4; i++) {
        int4 v = src[t + i * 256];
        ix[4 * i + 0] = v.x; ix[4 * i + 1] = v.y;
        ix[4 * i + 2] = v.z; ix[4 * i + 3] = v.w;
    }

    // Count above-window; histogram in-window bits (~8% of row)
    int chi = 0;
    #pragma unroll
    for (int e = 0; e < 16; e++) {
        int k = ix[e];
        if (k > IWHI) chi++;
        else if (k >= IWLO) atomicAdd(&S.hist[(unsigned)(IWHI - k) >> BSHIFT], 1u);
    }
    #pragma unroll
    for (int off = 16; off; off >>= 1)
        chi += __shfl_down_sync(0xffffffffu, chi, off);
    if (lane == 0) atomicAdd(&S.s_cnthi, (unsigned)chi);
    __syncthreads();

    // One-warp cumulative-from-top scan over the bins (bin 0 = largest)
    if (warp == 0) {
        const unsigned cnthi = S.s_cnthi;
        unsigned part = 0;
        #pragma unroll
        for (int i = 0; i < BPL; i++) part += S.hist[lane * BPL + i];
        unsigned pfx = part;
        #pragma unroll
        for (int s = 1; s < 32; s <<= 1) {
            unsigned v = __shfl_up_sync(0xffffffffu, pfx, s);
            if (lane >= s) pfx += v;
        }
        unsigned excl  = pfx - part;
        unsigned total = __shfl_sync(0xffffffffu, pfx, 31);
        unsigned base  = cnthi + excl;
        if (base < KSEL && base + part >= KSEL) {
            unsigned acc = base;
            #pragma unroll
            for (int i = 0; i < BPL; i++) {
                unsigned hv = S.hist[lane * BPL + i];
                if (acc + hv >= KSEL) { S.s_bin = lane * BPL + i; S.s_rem = (int)(KSEL - acc); break; }
                acc += hv;
            }
        }
        if (lane == 0 && (cnthi >= KSEL || cnthi + total < KSEL)) S.s_bin = -1; // fallback
    }
    __syncthreads();

    const int bin = S.s_bin;
    if (bin >= 0) {
        // Gather pivot-bin candidates (expected ~1), exact rank-select
        #pragma unroll
        for (int e = 0; e < 16; e++) {
            int k = ix[e];
            if (k <= IWHI && k >= IWLO && (int)((unsigned)(IWHI - k) >> BSHIFT) == bin) {
                unsigned p = atomicAdd(&S.s_ncand, 1u);
                if (p < MAXCAND) S.cand[p] = k;
            }
        }
        __syncthreads();
        unsigned nc = S.s_ncand;
        if (nc <= MAXCAND) {
            const int rem = S.s_rem;
            if (t < (int)nc) {
                int me = S.cand[t];     // positive bits: signed cmp = float cmp
                int gcnt = 0, eq = 0;
                for (unsigned j = 0; j < nc; j++) {
                    int v = S.cand[j];
                    gcnt += (v > me);
                    eq   += (v == me);
                }
                if (gcnt < rem && gcnt + eq >= rem) S.s_pivot = me;
            }
        } else {
            if (t == 0) S.s_bin = -1;   // overflow -> fallback
        }
        __syncthreads();
    }

    if (S.s_bin < 0) {
        // Exact fallback: MSB-first binary search on order-preserving keys
        unsigned piv = 0;
        for (int bit = 31; bit >= 0; --bit) {
            unsigned candv = piv | (1u << bit);
            int c = 0;
            #pragma unroll
            for (int e = 0; e < 16; e++) c += (fkey_bits((unsigned)ix[e]) >= candv);
            #pragma unroll
            for (int off = 16; off; off >>= 1)
                c += __shfl_down_sync(0xffffffffu, c, off);
            if (t == 0) S.s_tot = 0u;
            __syncthreads();
            if (lane == 0) atomicAdd(&S.s_tot, (unsigned)c);
            __syncthreads();
            if (S.s_tot >= KSEL) piv = candv;
            __syncthreads();
        }
        if (t == 0) S.s_pivot = unfkey_bits(piv);
        __syncthreads();
    }

    const int pivot = S.s_pivot;

    // Membership nibbles -> octet-shuffle merge -> OR into union bitset,
    // incremental popcount into S.s_cnt (leaders own distinct words).
    #pragma unroll
    for (int i = 0; i < 4; i++) {
        unsigned nib = 0;
        #pragma unroll
        for (int m = 0; m < 4; m++) nib |= (unsigned)(ix[4 * i + m] >= pivot) << m;
        unsigned wv = nib << (4 * (lane & 7));
        wv |= __shfl_xor_sync(0xffffffffu, wv, 1);
        wv |= __shfl_xor_sync(0xffffffffu, wv, 2);
        wv |= __shfl_xor_sync(0xffffffffu, wv, 4);
        if ((lane & 7) == 0) {
            int idx = 32 * i + 4 * warp + (lane >> 3);
            unsigned old = S.su[idx];
            unsigned nw  = old | wv;
            if (nw != old) {
                S.su[idx] = nw;
                atomicAdd(&S.s_cnt, __popc(nw & ~old));
            }
        }
    }
    __syncthreads();
}

// ---------------------------------------------------------------------------
// Kernel 1: lazy back-to-front selection. One block per head; computes row
// top-k masks ON DEMAND from the last row backwards, stopping when the union
// reaches THRESH (~3 rows for this input; exact up to the full LQ scan for
// any input). One monotonic global barrier for the n_stop coupling, then
// extends the union to n_stop rows and publishes it.
// ---------------------------------------------------------------------------
__global__ void __launch_bounds__(256) k_sel(const float* __restrict__ scores) {
    __shared__ ShState S;
    const int h = blockIdx.x, t = threadIdx.x;
    const int lane = t & 31, warp = t >> 5;

    if (t < WORDS) S.su[t] = 0u;
    if (t == 0) { S.s_cnt = 0; S.s_found = 0; }
    __syncthreads();

    const int4* base = (const int4*)(scores + (size_t)h * LQ * LK);

    // Phase 1: scan from the back until the union reaches THRESH
    for (int n = 1; n <= LQ; n++) {
        row_union(S, base + (size_t)(LQ - n) * (LK / 4), t, lane, warp);
        if (t == 0 && !S.s_found && S.s_cnt >= THRESH) S.s_found = n;
        __syncthreads();
        if (S.s_found) break;           // uniform: decided from shared state
    }
    if (t == 0) {
        g_nsel[h] = S.s_found ? S.s_found : NOT_CHOSEN;
        __threadfence();
        atomicAdd(&g_bar1, 1u);
    }
    // Monotonic counter barrier across the 32 co-resident blocks: each
    // execution adds exactly H, so value % H == 0 <=> all arrived (polled
    // only after own arrival).
    if (t == 0) {
        volatile unsigned* vb = &g_bar1;
        while ((*vb & (H - 1)) != 0u) {}
    }
    __syncthreads();
    __threadfence();

    // n_stop = all heads chosen ? max(nsel) : LQ   (warp 0 computes)
    if (warp == 0) {
        int v  = g_nsel[lane];
        int ch = (v < NOT_CHOSEN) ? 1 : 0;
        int mx = ch ? v : 1;
        #pragma unroll
        for (int off = 16; off; off >>= 1) {
            ch = min(ch, __shfl_down_sync(0xffffffffu, ch, off));
            mx = max(mx, __shfl_down_sync(0xffffffffu, mx, off));
        }
        if (lane == 0) S.s_nstop = ch ? mx : LQ;
    }
    __syncthreads();

    // Phase 2: extend this head's union to cover the last n_stop rows
    const int ns    = S.s_nstop;
    const int start = (S.s_found ? S.s_found : LQ) + 1;
    for (int n = start; n <= ns; n++)
        row_union(S, base + (size_t)(LQ - n) * (LK / 4), t, lane, warp);

    if (t < WORDS) g_hunion[h * WORDS + t] = S.su[t];
}

// ---------------------------------------------------------------------------
// Kernel 2 (after the output memset): group-OR, last-row write, density.
// grid = H blocks, 256 threads; block h writes head h's last row.
// ---------------------------------------------------------------------------
__global__ void __launch_bounds__(256) k_fin(float* __restrict__ out, int write_density) {
    const int h = blockIdx.x, t = threadIdx.x;
    const int g = h / GS, lane = t & 31, warp = t >> 5;
    __shared__ unsigned su[WORDS];
    __shared__ int ws[8];

    if (t < WORDS)
        su[t] = g_hunion[(g * GS + 0) * WORDS + t]
              | g_hunion[(g * GS + 1) * WORDS + t]
              | g_hunion[(g * GS + 2) * WORDS + t]
              | g_hunion[(g * GS + 3) * WORDS + t];
    __syncthreads();

    const float MINV = -3.402823466e38f;  // finfo(float32).min
    float* orow = out + ((size_t)h * LQ + (LQ - 1)) * LK;
    #pragma unroll
    for (int i = 0; i < 4; i++) {
        int c4 = t + i * 256;              // float4 index; cols 4*c4..4*c4+3
        unsigned w = su[c4 >> 3];
        float4 v;
        v.x = ((w >> ((4 * c4 + 0) & 31)) & 1u) ? 0.0f : MINV;
        v.y = ((w >> ((4 * c4 + 1) & 31)) & 1u) ? 0.0f : MINV;
        v.z = ((w >> ((4 * c4 + 2) & 31)) & 1u) ? 0.0f : MINV;
        v.w = ((w >> ((4 * c4 + 3) & 31)) & 1u) ? 0.0f : MINV;
        ((float4*)orow)[c4] = v;
    }

    // Density over all 8 group unions (block 0 only; uniform per block)
    if (write_density && h == 0) {
        int c = 0;
        for (int p = t; p < NG * WORDS; p += 256) {
            int gg = p >> 7, w = p & 127;
            unsigned gu = g_hunion[(gg * GS + 0) * WORDS + w]
                        | g_hunion[(gg * GS + 1) * WORDS + w]
                        | g_hunion[(gg * GS + 2) * WORDS + w]
                        | g_hunion[(gg * GS + 3) * WORDS + w];
            c += __popc(gu);
        }
        #pragma unroll
        for (int off = 16; off; off >>= 1)
            c += __shfl_down_sync(0xffffffffu, c, off);
        if (lane == 0) ws[warp] = c;
        __syncthreads();
        if (t == 0) {
            int total = 0;
            #pragma unroll
            for (int w = 0; w < 8; w++) total += ws[w];
            out[(size_t)H * LQ * LK] = (float)(GS * total) / (float)(H * LK);
        }
    }
}

// ---------------------------------------------------------------------------
extern "C" void kernel_launch(void* const* d_in, const int* in_sizes, int n_in,
                              void* d_out, int out_size) {
    const float* scores = (const float*)d_in[0];
    float* out = (float*)d_out;

    k_sel<<<H, 256>>>(scores);                                   // ~4 MB of reads
    cudaMemsetAsync(d_out, 0, (size_t)out_size * sizeof(float), 0);  // the 256 MB
    k_fin<<<H, 256>>>(out, out_size > H * LQ * LK ? 1 : 0);      // last rows + density
}